// round 9
// baseline (speedup 1.0000x reference)
#include <cuda_runtime.h>
#include <math.h>

// Problem shape (fixed by reference setup_inputs)
#define BATCH 2048
#define NLABELS 50000
#define NTRIALS 64

// One warp per row; lanes 0..15 probe trials 0..15 in one ballot.
// P(row unresolved after 16 trials) ~ 0.24^16 ~ 1e-10 on this data; the
// guarded 16-lane rounds over trials 16..63 keep exactness for ANY input.
#define PROBE 16
#define WARPS_PER_BLOCK 8
#define THREADS_PER_BLOCK (WARPS_PER_BLOCK * 32)   // 256
#define NUM_BLOCKS (BATCH / WARPS_PER_BLOCK)       // 256 (best-known envelope)

// Per-row losses (no allocations allowed anywhere).
__device__ float g_row_loss[BATCH];

__global__ void __launch_bounds__(THREADS_PER_BLOCK)
warp_loss_main(const float* __restrict__ inp,
               const int* __restrict__ pos_idx,
               const int* __restrict__ neg_cands)
{
    const int lane = threadIdx.x & 31;
    const int wid  = threadIdx.x >> 5;
    const int row  = blockIdx.x * WARPS_PER_BLOCK + wid;

    const long  base  = (long)row * NLABELS;
    const bool  active = (lane < PROBE);

    // Independent 2-deep chains, issued up front:
    const int   p     = __ldg(pos_idx + row);                     // broadcast
    const int   idx0  = active ? __ldg(neg_cands + row * NTRIALS + lane) : 0;
    const float pos_s = __ldg(inp + base + p);                    // 1 line/row
    const float neg0  = active ? __ldg(inp + base + idx0) : 0.0f; // 16 gathers
    const float thr   = pos_s - 1.0f;                // margin>=0 <=> neg>=thr

    // ---- trials 0..15: one ballot over the low 16 lanes ----
    const unsigned m0 = __ballot_sync(0xffffffffu, active && (neg0 >= thr));

    float loss = 0.0f;
    bool  done = false;
    if (m0) {
        const int   first = __ffs(m0) - 1;
        const float sel   = __shfl_sync(0xffffffffu, neg0, first);
        if (lane == 0) {
            const float nt = (float)(first + 1);
            const float L  = logf(floorf((float)(NLABELS - 1) / nt));
            loss = L * (1.0f - pos_s + sel);
        }
        done = true;
    }

    // ---- fallback rounds: trials 16..63 (statistically never taken) ----
    if (!done) {
        #pragma unroll 1
        for (int k = 1; k < NTRIALS / PROBE; k++) {
            const int trial = k * PROBE + lane;
            float neg = 0.0f;
            if (active) {
                const int idx = __ldg(neg_cands + row * NTRIALS + trial);
                neg = __ldg(inp + base + idx);
            }
            const unsigned m = __ballot_sync(0xffffffffu, active && (neg >= thr));
            if (m) {
                const int   f   = __ffs(m) - 1;
                const float sel = __shfl_sync(0xffffffffu, neg, f);
                if (lane == 0) {
                    const float nt = (float)(k * PROBE + f + 1);
                    const float L  = logf(floorf((float)(NLABELS - 1) / nt));
                    loss = L * (1.0f - pos_s + sel);
                }
                break;
            }
        }
        // no accepted negative in any round -> loss stays 0 (matches reference)
    }

    // Decoupled retire: no barrier, no smem — warps drain independently.
    if (lane == 0) g_row_loss[row] = loss;
}

// Second graph node: 256 threads sum 2048 row losses in fixed order (L2-hot).
__global__ void __launch_bounds__(256)
warp_loss_reduce(float* __restrict__ out)
{
    const int t    = threadIdx.x;
    const int lane = t & 31;
    const int wid  = t >> 5;

    float v = 0.0f;
    #pragma unroll
    for (int j = 0; j < BATCH / 256; j++)          // 8 strided reads / thread
        v += g_row_loss[t + j * 256];
    #pragma unroll
    for (int off = 16; off >= 1; off >>= 1)
        v += __shfl_xor_sync(0xffffffffu, v, off);

    __shared__ float s[8];
    if (lane == 0) s[wid] = v;
    __syncthreads();
    if (t == 0) {
        float sum = 0.0f;
        #pragma unroll
        for (int i = 0; i < 8; i++) sum += s[i];
        out[0] = sum;
    }
}

extern "C" void kernel_launch(void* const* d_in, const int* in_sizes, int n_in,
                              void* d_out, int out_size)
{
    // metadata order: input (f32 [B,Y]), target (i32, UNUSED), pos_idx (i32 [B]),
    //                 neg_cands (i32 [B,T]); output f32 [1]
    const float* inp     = (const float*)d_in[0];
    const int*   pos_idx = (const int*)d_in[2];
    const int*   neg     = (const int*)d_in[3];
    float*       out     = (float*)d_out;

    warp_loss_main<<<NUM_BLOCKS, THREADS_PER_BLOCK>>>(inp, pos_idx, neg);
    warp_loss_reduce<<<1, 256>>>(out);
}

// round 11
// speedup vs baseline: 1.2444x; 1.2444x over previous
#include <cuda_runtime.h>
#include <math.h>

// Problem shape (fixed by reference setup_inputs)
#define BATCH 2048
#define NLABELS 50000
#define NTRIALS 64

// One warp per row; lane = trial. One ballot resolves trials 0..31.
// P(row unresolved after 32 trials) ~ 0.24^32 ~ 1e-20 on this data;
// the guarded fallback over trials 32..63 keeps exactness for ANY input.
#define WARPS_PER_BLOCK 8
#define THREADS_PER_BLOCK (WARPS_PER_BLOCK * 32)   // 256
#define NUM_BLOCKS (BATCH / WARPS_PER_BLOCK)       // 256  (best-known envelope)

// Scratch partials (no allocations allowed anywhere).
__device__ float g_partials[NUM_BLOCKS];

__global__ void __launch_bounds__(THREADS_PER_BLOCK)
warp_loss_main(const float* __restrict__ inp,
               const int* __restrict__ pos_idx,
               const int* __restrict__ neg_cands)
{
    const int lane = threadIdx.x & 31;
    const int wid  = threadIdx.x >> 5;
    const int row  = blockIdx.x * WARPS_PER_BLOCK + wid;

    const long  base  = (long)row * NLABELS;
    // Independent 2-deep chains, all issued up front:
    const int   p     = __ldg(pos_idx + row);                    // broadcast
    const int   idx0  = __ldg(neg_cands + row * NTRIALS + lane); // coalesced
    const float pos_s = __ldg(inp + base + p);                   // 1 line/row
    const float neg0  = __ldg(inp + base + idx0);                // random gather
    const float thr   = pos_s - 1.0f;               // margin>=0 <=> neg>=thr

    // ---- trials 0..31: one ballot ----
    const unsigned m0 = __ballot_sync(0xffffffffu, neg0 >= thr);

    float loss = 0.0f;
    if (m0) {
        const int   first = __ffs(m0) - 1;
        const float sel   = __shfl_sync(0xffffffffu, neg0, first);
        if (lane == 0) {
            const float nt = (float)(first + 1);
            const float L  = logf(floorf((float)(NLABELS - 1) / nt));
            loss = L * (1.0f - pos_s + sel);
        }
    } else {
        // ---- fallback: trials 32..63 (statistically never taken) ----
        const int   idx1 = __ldg(neg_cands + row * NTRIALS + 32 + lane);
        const float neg1 = __ldg(inp + base + idx1);
        const unsigned m1 = __ballot_sync(0xffffffffu, neg1 >= thr);
        if (m1) {
            const int   f   = __ffs(m1) - 1;
            const float sel = __shfl_sync(0xffffffffu, neg1, f);
            if (lane == 0) {
                const float nt = (float)(32 + f + 1);
                const float L  = logf(floorf((float)(NLABELS - 1) / nt));
                loss = L * (1.0f - pos_s + sel);
            }
        }
        // else: no accepted negative -> loss stays 0 (matches reference).
    }

    // ---- block partial: lane 0 of each warp holds the row loss ----
    __shared__ float s_warp[WARPS_PER_BLOCK];
    if (lane == 0) s_warp[wid] = loss;
    __syncthreads();
    if (threadIdx.x == 0) {
        float sum = 0.0f;
        #pragma unroll
        for (int i = 0; i < WARPS_PER_BLOCK; i++) sum += s_warp[i];
        g_partials[blockIdx.x] = sum;
    }
}

// Second graph node, launched with PDL: its launch preamble overlaps the
// primary kernel's execution; cudaGridDependencySynchronize() blocks until
// the primary grid (and all its memory ops) completes before we read.
__global__ void __launch_bounds__(32)
warp_loss_reduce(float* __restrict__ out)
{
    cudaGridDependencySynchronize();

    const int lane = threadIdx.x;
    float v = 0.0f;
    #pragma unroll
    for (int j = 0; j < NUM_BLOCKS / 32; j++)
        v += g_partials[lane + j * 32];
    #pragma unroll
    for (int off = 16; off >= 1; off >>= 1)
        v += __shfl_xor_sync(0xffffffffu, v, off);
    if (lane == 0) out[0] = v;
}

extern "C" void kernel_launch(void* const* d_in, const int* in_sizes, int n_in,
                              void* d_out, int out_size)
{
    // metadata order: input (f32 [B,Y]), target (i32, UNUSED), pos_idx (i32 [B]),
    //                 neg_cands (i32 [B,T]); output f32 [1]
    const float* inp     = (const float*)d_in[0];
    const int*   pos_idx = (const int*)d_in[2];
    const int*   neg     = (const int*)d_in[3];
    float*       out     = (float*)d_out;

    warp_loss_main<<<NUM_BLOCKS, THREADS_PER_BLOCK>>>(inp, pos_idx, neg);

    // PDL launch of the reduce node: overlap its prologue with the main grid.
    cudaLaunchConfig_t cfg = {};
    cfg.gridDim  = dim3(1, 1, 1);
    cfg.blockDim = dim3(32, 1, 1);
    cfg.dynamicSmemBytes = 0;
    cfg.stream = 0;   // same (capture) stream as the primary launch
    cudaLaunchAttribute attr[1];
    attr[0].id = cudaLaunchAttributeProgrammaticStreamSerialization;
    attr[0].val.programmaticStreamSerializationAllowed = 1;
    cfg.attrs = attr;
    cfg.numAttrs = 1;
    cudaLaunchKernelEx(&cfg, warp_loss_reduce, out);
}

// round 12
// speedup vs baseline: 1.2537x; 1.0075x over previous
#include <cuda_runtime.h>
#include <math.h>

// Problem shape (fixed by reference setup_inputs)
#define BATCH 2048
#define NLABELS 50000
#define NTRIALS 64

// One warp per row; lane = trial. One ballot resolves trials 0..31.
// P(row unresolved after 32 trials) ~ 0.24^32 ~ 1e-20 on this data;
// the guarded fallback over trials 32..63 keeps exactness for ANY input.
#define WARPS_PER_BLOCK 8
#define THREADS_PER_BLOCK (WARPS_PER_BLOCK * 32)   // 256
#define NUM_BLOCKS (BATCH / WARPS_PER_BLOCK)       // 256  (best-known envelope)

// Scratch partials (no allocations allowed anywhere).
__device__ float g_partials[NUM_BLOCKS];
// atomicInc with limit NUM_BLOCKS-1 wraps to 0 on the last arrival ->
// counter auto-resets for every graph replay.
__device__ unsigned int g_arrive = 0;

__global__ void __launch_bounds__(THREADS_PER_BLOCK)
warp_loss_fused(const float* __restrict__ inp,
                const int* __restrict__ pos_idx,
                const int* __restrict__ neg_cands,
                float* __restrict__ out)
{
    const int lane = threadIdx.x & 31;
    const int wid  = threadIdx.x >> 5;
    const int row  = blockIdx.x * WARPS_PER_BLOCK + wid;

    const long  base  = (long)row * NLABELS;
    // Independent 2-deep chains, all issued up front:
    const int   p     = __ldg(pos_idx + row);                    // broadcast
    const int   idx0  = __ldg(neg_cands + row * NTRIALS + lane); // coalesced
    const float pos_s = __ldg(inp + base + p);                   // 1 line/row
    const float neg0  = __ldg(inp + base + idx0);                // random gather
    const float thr   = pos_s - 1.0f;               // margin>=0 <=> neg>=thr

    // ---- trials 0..31: one ballot ----
    const unsigned m0 = __ballot_sync(0xffffffffu, neg0 >= thr);

    float loss = 0.0f;
    if (m0) {
        const int   first = __ffs(m0) - 1;
        const float sel   = __shfl_sync(0xffffffffu, neg0, first);
        if (lane == 0) {
            const float nt = (float)(first + 1);
            const float L  = logf(floorf((float)(NLABELS - 1) / nt));
            loss = L * (1.0f - pos_s + sel);
        }
    } else {
        // ---- fallback: trials 32..63 (statistically never taken) ----
        const int   idx1 = __ldg(neg_cands + row * NTRIALS + 32 + lane);
        const float neg1 = __ldg(inp + base + idx1);
        const unsigned m1 = __ballot_sync(0xffffffffu, neg1 >= thr);
        if (m1) {
            const int   f   = __ffs(m1) - 1;
            const float sel = __shfl_sync(0xffffffffu, neg1, f);
            if (lane == 0) {
                const float nt = (float)(32 + f + 1);
                const float L  = logf(floorf((float)(NLABELS - 1) / nt));
                loss = L * (1.0f - pos_s + sel);
            }
        }
        // else: no accepted negative -> loss stays 0 (matches reference).
    }

    // ---- block partial: lane 0 of each warp holds the row loss ----
    __shared__ float s_warp[WARPS_PER_BLOCK];
    __shared__ bool  s_is_last;
    if (lane == 0) s_warp[wid] = loss;
    __syncthreads();
    if (threadIdx.x == 0) {
        float sum = 0.0f;
        #pragma unroll
        for (int i = 0; i < WARPS_PER_BLOCK; i++) sum += s_warp[i];
        g_partials[blockIdx.x] = sum;
        __threadfence();                      // partial visible GPU-wide
        unsigned old = atomicInc(&g_arrive, NUM_BLOCKS - 1);  // wraps -> reset
        s_is_last = (old == NUM_BLOCKS - 1);
    }
    __syncthreads();

    // Last-arriving block, warp 0: fixed-order sum of 256 partials (L2-hot).
    if (s_is_last && wid == 0) {
        float v = 0.0f;
        #pragma unroll
        for (int j = 0; j < NUM_BLOCKS / 32; j++)
            v += g_partials[lane + j * 32];
        #pragma unroll
        for (int off = 16; off >= 1; off >>= 1)
            v += __shfl_xor_sync(0xffffffffu, v, off);
        if (lane == 0) out[0] = v;
    }
}

extern "C" void kernel_launch(void* const* d_in, const int* in_sizes, int n_in,
                              void* d_out, int out_size)
{
    // metadata order: input (f32 [B,Y]), target (i32, UNUSED), pos_idx (i32 [B]),
    //                 neg_cands (i32 [B,T]); output f32 [1]
    const float* inp     = (const float*)d_in[0];
    const int*   pos_idx = (const int*)d_in[2];
    const int*   neg     = (const int*)d_in[3];
    float*       out     = (float*)d_out;

    warp_loss_fused<<<NUM_BLOCKS, THREADS_PER_BLOCK>>>(inp, pos_idx, neg, out);
}

// round 13
// speedup vs baseline: 1.4802x; 1.1806x over previous
#include <cuda_runtime.h>
#include <math.h>

// Problem shape (fixed by reference setup_inputs)
#define BATCH 2048
#define NLABELS 50000
#define NTRIALS 64

// One warp per row. Lanes 0..15 probe trials 0..15; lanes 16..31 DUPLICATE
// those same addresses (lane & 15) so the warp still issues a full-width,
// unpredicated LDG whose 32 requests coalesce into only 16 distinct lines.
// P(row unresolved after 16 trials) ~ 0.24^16 ~ 1e-10 on this data; guarded
// 16-wide fallback rounds over trials 16..63 keep exactness for ANY input.
#define PROBE 16
#define WARPS_PER_BLOCK 8
#define THREADS_PER_BLOCK (WARPS_PER_BLOCK * 32)   // 256
#define NUM_BLOCKS (BATCH / WARPS_PER_BLOCK)       // 256  (best-known envelope)

// Scratch partials (no allocations allowed anywhere).
__device__ float g_partials[NUM_BLOCKS];
// atomicInc with limit NUM_BLOCKS-1 wraps to 0 on the last arrival ->
// counter auto-resets for every graph replay.
__device__ unsigned int g_arrive = 0;

__global__ void __launch_bounds__(THREADS_PER_BLOCK)
warp_loss_fused(const float* __restrict__ inp,
                const int* __restrict__ pos_idx,
                const int* __restrict__ neg_cands,
                float* __restrict__ out)
{
    const int lane = threadIdx.x & 31;
    const int sub  = lane & (PROBE - 1);            // duplicated trial slot
    const int wid  = threadIdx.x >> 5;
    const int row  = blockIdx.x * WARPS_PER_BLOCK + wid;

    const long  base  = (long)row * NLABELS;
    // Full-width unpredicated loads; upper half duplicates lower half's
    // addresses -> 16 distinct lines per gather instead of 32.
    const int   p     = __ldg(pos_idx + row);                    // broadcast
    const int   idx0  = __ldg(neg_cands + row * NTRIALS + sub);  // dup-coalesced
    const float pos_s = __ldg(inp + base + p);                   // 1 line/row
    const float neg0  = __ldg(inp + base + idx0);                // 16 lines/row
    const float thr   = pos_s - 1.0f;               // margin>=0 <=> neg>=thr

    // ---- trials 0..15: ballot, use low-16 bits only ----
    const unsigned m0 = __ballot_sync(0xffffffffu, neg0 >= thr) & 0xFFFFu;

    float loss = 0.0f;
    bool  done = (m0 != 0u);
    if (done) {
        const int   first = __ffs(m0) - 1;
        const float sel   = __shfl_sync(0xffffffffu, neg0, first);
        if (lane == 0) {
            const float nt = (float)(first + 1);
            const float L  = logf(floorf((float)(NLABELS - 1) / nt));
            loss = L * (1.0f - pos_s + sel);
        }
    } else {
        // ---- fallback rounds: trials 16..63 (statistically never taken) ----
        #pragma unroll 1
        for (int k = 1; k < NTRIALS / PROBE; k++) {
            const int   trial = k * PROBE + sub;
            const int   idx   = __ldg(neg_cands + row * NTRIALS + trial);
            const float neg   = __ldg(inp + base + idx);
            const unsigned m  = __ballot_sync(0xffffffffu, neg >= thr) & 0xFFFFu;
            if (m) {
                const int   f   = __ffs(m) - 1;
                const float sel = __shfl_sync(0xffffffffu, neg, f);
                if (lane == 0) {
                    const float nt = (float)(k * PROBE + f + 1);
                    const float L  = logf(floorf((float)(NLABELS - 1) / nt));
                    loss = L * (1.0f - pos_s + sel);
                }
                break;
            }
        }
        // no accepted negative anywhere -> loss stays 0 (matches reference)
    }

    // ---- block partial: lane 0 of each warp holds the row loss ----
    __shared__ float s_warp[WARPS_PER_BLOCK];
    __shared__ bool  s_is_last;
    if (lane == 0) s_warp[wid] = loss;
    __syncthreads();
    if (threadIdx.x == 0) {
        float sum = 0.0f;
        #pragma unroll
        for (int i = 0; i < WARPS_PER_BLOCK; i++) sum += s_warp[i];
        g_partials[blockIdx.x] = sum;
        __threadfence();                      // partial visible GPU-wide
        unsigned old = atomicInc(&g_arrive, NUM_BLOCKS - 1);  // wraps -> reset
        s_is_last = (old == NUM_BLOCKS - 1);
    }
    __syncthreads();

    // Last-arriving block, warp 0: fixed-order sum of 256 partials (L2-hot).
    if (s_is_last && wid == 0) {
        float v = 0.0f;
        #pragma unroll
        for (int j = 0; j < NUM_BLOCKS / 32; j++)
            v += g_partials[lane + j * 32];
        #pragma unroll
        for (int off = 16; off >= 1; off >>= 1)
            v += __shfl_xor_sync(0xffffffffu, v, off);
        if (lane == 0) out[0] = v;
    }
}

extern "C" void kernel_launch(void* const* d_in, const int* in_sizes, int n_in,
                              void* d_out, int out_size)
{
    // metadata order: input (f32 [B,Y]), target (i32, UNUSED), pos_idx (i32 [B]),
    //                 neg_cands (i32 [B,T]); output f32 [1]
    const float* inp     = (const float*)d_in[0];
    const int*   pos_idx = (const int*)d_in[2];
    const int*   neg     = (const int*)d_in[3];
    float*       out     = (float*)d_out;

    warp_loss_fused<<<NUM_BLOCKS, THREADS_PER_BLOCK>>>(inp, pos_idx, neg, out);
}